// round 3
// baseline (speedup 1.0000x reference)
#include <cuda_runtime.h>
#include <utility>

#define DH __host__ __device__

// ---------------- compile-time Clebsch-Gordan machinery ----------------

DH constexpr int cabsi(int a) { return a < 0 ? -a : a; }
DH constexpr int cmini(int a, int b) { return a < b ? a : b; }

DH constexpr double cfact(int n) {
    double r = 1.0;
    for (int i = 2; i <= n; ++i) r *= (double)i;
    return r;
}

DH constexpr double csqrt(double x) {
    if (x <= 0.0) return 0.0;
    double g = x < 1.0 ? 1.0 : x;
    for (int i = 0; i < 200; ++i) g = 0.5 * (g + x / g);
    return g;
}

// Condon-Shortley CG coefficient (Racah formula), compile-time, mirrors reference.
DH constexpr double cg_coef(int j1, int m1, int j2, int m2, int j3, int m3) {
    if (m1 + m2 != m3) return 0.0;
    if (j3 < cabsi(j1 - j2) || j3 > j1 + j2) return 0.0;
    double pref = csqrt((2.0 * j3 + 1.0) * cfact(j3 + j1 - j2) * cfact(j3 - j1 + j2)
                        * cfact(j1 + j2 - j3) / cfact(j1 + j2 + j3 + 1));
    pref *= csqrt(cfact(j3 + m3) * cfact(j3 - m3) * cfact(j1 - m1) * cfact(j1 + m1)
                  * cfact(j2 - m2) * cfact(j2 + m2));
    double s = 0.0;
    for (int k = 0; k <= j1 + j2 - j3; ++k) {
        int a2 = j1 + j2 - j3 - k, a3 = j1 - m1 - k, a4 = j2 + m2 - k;
        int a5 = j3 - j2 + m1 + k, a6 = j3 - j1 - m2 + k;
        if (a2 < 0 || a3 < 0 || a4 < 0 || a5 < 0 || a6 < 0) continue;
        double den = cfact(k) * cfact(a2) * cfact(a3) * cfact(a4) * cfact(a5) * cfact(a6);
        s += ((k & 1) ? -1.0 : 1.0) / den;
    }
    return pref * s;
}

// ---------------- problem geometry (compile-time) ----------------

constexpr int TOTAL_IN = 2304;       // floats per batch row
constexpr long OUT_POS = 789504;     // float2 (re,im) positions per batch row

DH constexpr bool tvalid(int l, int l1, int l2) {
    return cabsi(l1 - l2) <= l && l <= l1 + l2;
}
DH constexpr int ntup(int l) {
    int c = 0;
    for (int l1 = 0; l1 <= 5; ++l1)
        for (int l2 = 0; l2 <= 5; ++l2)
            if (tvalid(l, l1, l2)) ++c;
    return c;
}
DH constexpr long outbase(int l) {
    long s = 0;
    for (int lp = 0; lp < l; ++lp) s += (long)ntup(lp) * 1024 * (2 * lp + 1);
    return s;
}
DH constexpr int pair_rank(int l, int L1, int L2) {
    int r = 0;
    for (int l1 = 0; l1 <= 5; ++l1)
        for (int l2 = 0; l2 <= 5; ++l2)
            if ((l1 < L1 || (l1 == L1 && l2 < L2)) && tvalid(l, l1, l2)) ++r;
    return r;
}

// ---------------- job table: pairs split into l-subranges, NACC <= 20 ----------------
// Each job = (l1, l2, llo, lhi). Emitted heavy-first (descending l1+l2).

struct JobsT {
    int n;
    int l1[96], l2[96], llo[96], lhi[96];
};

constexpr JobsT make_jobs() {
    JobsT js{};
    js.n = 0;
    for (int s = 10; s >= 0; --s)
        for (int a = 0; a <= 5; ++a)
            for (int b = 0; b <= 5; ++b) {
                if (a + b != s) continue;
                const int lmin = cabsi(a - b);
                const int lmx = cmini(5, a + b);
                int lo = lmin;
                while (lo <= lmx) {
                    int hi = lo, acc = 2 * lo + 1;
                    while (hi < lmx && acc + 2 * (hi + 1) + 1 <= 20) {
                        ++hi;
                        acc += 2 * hi + 1;
                    }
                    js.l1[js.n] = a; js.l2[js.n] = b;
                    js.llo[js.n] = lo; js.lhi[js.n] = hi;
                    ++js.n;
                    lo = hi + 1;
                }
            }
    return js;
}

constexpr JobsT JOBS = make_jobs();
constexpr int NJOBS = JOBS.n;

// ---------------- static_for helper ----------------

template <class F, int... Is>
__device__ __forceinline__ void sfor_impl(F&& f, std::integer_sequence<int, Is...>) {
    (f(std::integral_constant<int, Is>{}), ...);
}
template <int N, class F>
__device__ __forceinline__ void sfor(F&& f) {
    sfor_impl(f, std::make_integer_sequence<int, N>{});
}

// per-warp shared staging for writeback: 32 t-values x up to 11 float2
constexpr int STAGE_F2 = 32 * 11;

// ---------------- per-job fully-unrolled worker ----------------

template <int L1, int L2, int LLO, int LHI>
__device__ __forceinline__ void do_job(const float* __restrict__ fs,
                                       float2* __restrict__ out,
                                       float2* __restrict__ ws,      // warp writeback stage
                                       float2* __restrict__ bstage,  // block b-fragment stage
                                       int b, int t) {
    constexpr int M1 = 2 * L1 + 1;
    constexpr int M2 = 2 * L2 + 1;
    constexpr int NL = LHI - LLO + 1;
    constexpr int NACC = (LHI + 1) * (LHI + 1) - LLO * LLO;

    const int t1 = t >> 5;
    const int t2 = t & 31;  // lane id

    // ---- stage b-fragment (32 taus x M2 float2, contiguous) into smem, coalesced ----
    {
        const float4* __restrict__ src =
            reinterpret_cast<const float4*>(fs + (long)b * TOTAL_IN + 64 * L2 * L2);
        if (threadIdx.x < 16 * M2)
            reinterpret_cast<float4*>(bstage)[threadIdx.x] = src[threadIdx.x];
    }
    __syncthreads();

    float2 bv[M2];
#pragma unroll
    for (int i = 0; i < M2; ++i) bv[i] = bstage[t2 * M2 + i];

    float2 acc[NACC];
#pragma unroll
    for (int i = 0; i < NACC; ++i) acc[i] = make_float2(0.f, 0.f);

    const float2* __restrict__ arow =
        reinterpret_cast<const float2*>(fs + (long)b * TOTAL_IN + 64 * L1 * L1 + t1 * M1 * 2);

    sfor<M1>([&](auto I1) {
        constexpr int im1 = decltype(I1)::value;
        const float2 av = arow[im1];  // warp-uniform broadcast LDG
        sfor<M2>([&](auto I2) {
            constexpr int im2 = decltype(I2)::value;
            constexpr int m = (im1 - L1) + (im2 - L2);
            if constexpr (m >= -LHI && m <= LHI) {
                const float pr = av.x * bv[im2].x - av.y * bv[im2].y;
                const float pi = av.x * bv[im2].y + av.y * bv[im2].x;
                sfor<NL>([&](auto J) {
                    constexpr int l = LLO + decltype(J)::value;
                    if constexpr (m >= -l && m <= l) {
                        constexpr float c =
                            (float)cg_coef(L1, im1 - L1, L2, im2 - L2, l, m);
                        if constexpr (c != 0.0f) {
                            constexpr int ao = (l * l - LLO * LLO) + (m + l);
                            acc[ao].x += c * pr;  // FFMA-imm
                            acc[ao].y += c * pi;
                        }
                    }
                });
            }
        });
    });

    // ---- writeback: per degree l, smem transpose -> coalesced float4 stores ----
    const long obatch = (long)b * OUT_POS;
    sfor<NL>([&](auto J) {
        constexpr int l = LLO + decltype(J)::value;
        constexpr int NM = 2 * l + 1;
        constexpr long pbase = outbase(l) + (long)pair_rank(l, L1, L2) * 1024 * NM;

        __syncwarp();
#pragma unroll
        for (int mm = 0; mm < NM; ++mm)
            ws[t2 * NM + mm] = acc[(l * l - LLO * LLO) + mm];
        __syncwarp();

        const float4* __restrict__ s4 = reinterpret_cast<const float4*>(ws);
        float4* __restrict__ o4 = reinterpret_cast<float4*>(
            out + obatch + pbase + (long)(t & ~31) * NM);
        constexpr int CNT4 = 16 * NM;
#pragma unroll
        for (int i = 0; i < (CNT4 + 31) / 32; ++i) {
            const int idx = i * 32 + t2;
            if (CNT4 % 32 == 0 || idx < CNT4) o4[idx] = s4[idx];
        }
    });
}

// ---------------- kernel: NJOBS jobs x 32 batches x 4 t-tiles, 256 thr/blk ----------------

__global__ void __launch_bounds__(256, 3)
cg_kernel(const float* __restrict__ fs, float2* __restrict__ out) {
    __shared__ float2 bstage[32 * 11];
    __shared__ float2 stage[8][STAGE_F2];

    const int bid = blockIdx.x;
    const int jid = bid >> 7;          // jobs already ordered heavy-first
    const int r = bid & 127;
    const int b = r >> 2;
    const int t = ((r & 3) << 8) + threadIdx.x;
    float2* ws = stage[threadIdx.x >> 5];

    sfor<NJOBS>([&](auto J) {
        constexpr int jj = decltype(J)::value;
        if (jid == jj)
            do_job<JOBS.l1[jj], JOBS.l2[jj], JOBS.llo[jj], JOBS.lhi[jj]>(
                fs, out, ws, bstage, b, t);
    });
}

extern "C" void kernel_launch(void* const* d_in, const int* in_sizes, int n_in,
                              void* d_out, int out_size) {
    const float* fs = (const float*)d_in[0];
    float2* out = (float2*)d_out;
    cg_kernel<<<NJOBS * 128, 256>>>(fs, out);
}

// round 6
// speedup vs baseline: 1.1063x; 1.1063x over previous
#include <cuda_runtime.h>
#include <utility>

#define DH __host__ __device__

// ---------------- compile-time Clebsch-Gordan machinery ----------------

DH constexpr int cabsi(int a) { return a < 0 ? -a : a; }
DH constexpr int cmini(int a, int b) { return a < b ? a : b; }

DH constexpr double cfact(int n) {
    double r = 1.0;
    for (int i = 2; i <= n; ++i) r *= (double)i;
    return r;
}

DH constexpr double csqrt(double x) {
    if (x <= 0.0) return 0.0;
    double g = x < 1.0 ? 1.0 : x;
    for (int i = 0; i < 200; ++i) g = 0.5 * (g + x / g);
    return g;
}

// Condon-Shortley CG coefficient (Racah formula), compile-time, mirrors reference.
DH constexpr double cg_coef(int j1, int m1, int j2, int m2, int j3, int m3) {
    if (m1 + m2 != m3) return 0.0;
    if (j3 < cabsi(j1 - j2) || j3 > j1 + j2) return 0.0;
    double pref = csqrt((2.0 * j3 + 1.0) * cfact(j3 + j1 - j2) * cfact(j3 - j1 + j2)
                        * cfact(j1 + j2 - j3) / cfact(j1 + j2 + j3 + 1));
    pref *= csqrt(cfact(j3 + m3) * cfact(j3 - m3) * cfact(j1 - m1) * cfact(j1 + m1)
                  * cfact(j2 - m2) * cfact(j2 + m2));
    double s = 0.0;
    for (int k = 0; k <= j1 + j2 - j3; ++k) {
        int a2 = j1 + j2 - j3 - k, a3 = j1 - m1 - k, a4 = j2 + m2 - k;
        int a5 = j3 - j2 + m1 + k, a6 = j3 - j1 - m2 + k;
        if (a2 < 0 || a3 < 0 || a4 < 0 || a5 < 0 || a6 < 0) continue;
        double den = cfact(k) * cfact(a2) * cfact(a3) * cfact(a4) * cfact(a5) * cfact(a6);
        s += ((k & 1) ? -1.0 : 1.0) / den;
    }
    return pref * s;
}

// ---------------- problem geometry (compile-time) ----------------

constexpr int TOTAL_IN = 2304;       // floats per batch row
constexpr long OUT_POS = 789504;     // float2 (re,im) positions per batch row

DH constexpr bool tvalid(int l, int l1, int l2) {
    return cabsi(l1 - l2) <= l && l <= l1 + l2;
}
DH constexpr int ntup(int l) {
    int c = 0;
    for (int l1 = 0; l1 <= 5; ++l1)
        for (int l2 = 0; l2 <= 5; ++l2)
            if (tvalid(l, l1, l2)) ++c;
    return c;
}
DH constexpr long outbase(int l) {
    long s = 0;
    for (int lp = 0; lp < l; ++lp) s += (long)ntup(lp) * 1024 * (2 * lp + 1);
    return s;
}
DH constexpr int pair_rank(int l, int L1, int L2) {
    int r = 0;
    for (int l1 = 0; l1 <= 5; ++l1)
        for (int l2 = 0; l2 <= 5; ++l2)
            if ((l1 < L1 || (l1 == L1 && l2 < L2)) && tvalid(l, l1, l2)) ++r;
    return r;
}

// ---------------- job table: l1<=l2 pairs split into l-subranges, NACC <= 20 ----------

struct JobsT {
    int n;
    int l1[64], l2[64], llo[64], lhi[64];
};

constexpr JobsT make_jobs() {
    JobsT js{};
    js.n = 0;
    for (int s = 10; s >= 0; --s)
        for (int a = 0; a <= 5; ++a)
            for (int b = a; b <= 5; ++b) {  // only l1 <= l2 (mirror emitted for free)
                if (a + b != s) continue;
                const int lmin = b - a;
                const int lmx = cmini(5, a + b);
                int lo = lmin;
                while (lo <= lmx) {
                    int hi = lo, acc = 2 * lo + 1;
                    while (hi < lmx && acc + 2 * (hi + 1) + 1 <= 20) {
                        ++hi;
                        acc += 2 * hi + 1;
                    }
                    js.l1[js.n] = a; js.l2[js.n] = b;
                    js.llo[js.n] = lo; js.lhi[js.n] = hi;
                    ++js.n;
                    lo = hi + 1;
                }
            }
    return js;
}

constexpr JobsT JOBS = make_jobs();
constexpr int NJOBS = JOBS.n;

// ---------------- static_for helper ----------------

template <class F, int... Is>
__device__ __forceinline__ void sfor_impl(F&& f, std::integer_sequence<int, Is...>) {
    (f(std::integral_constant<int, Is>{}), ...);
}
template <int N, class F>
__device__ __forceinline__ void sfor(F&& f) {
    sfor_impl(f, std::make_integer_sequence<int, N>{});
}

// union staging buffer (float2):
//   direct phase: 8 warps x 352 (= 32 taus x up to 11 m)      -> 2816
//   mirror phase: 32 segments x (8*NM + 1 pad), NM <= 11      -> 2848
constexpr int UNION_F2 = 2848;

// ---------------- per-job fully-unrolled worker ----------------

template <int L1, int L2, int LLO, int LHI>
__device__ __forceinline__ void do_job(const float* __restrict__ fs,
                                       float2* __restrict__ out,
                                       float2* __restrict__ sm,      // union stage
                                       float2* __restrict__ bstage,  // b-fragment stage
                                       int b, int t) {
    constexpr int M1 = 2 * L1 + 1;
    constexpr int M2 = 2 * L2 + 1;
    constexpr int NL = LHI - LLO + 1;
    constexpr int NACC = (LHI + 1) * (LHI + 1) - LLO * LLO;

    const int t1 = t >> 5;
    const int t2 = t & 31;      // lane id
    const int w = threadIdx.x >> 5;
    const int t1lo = (t >> 5) & ~7;  // first t1 of this block's tile

    // ---- stage b-fragment (32 taus x M2 float2, contiguous) into smem, coalesced ----
    {
        const float4* __restrict__ src =
            reinterpret_cast<const float4*>(fs + (long)b * TOTAL_IN + 64 * L2 * L2);
        if (threadIdx.x < 16 * M2)
            reinterpret_cast<float4*>(bstage)[threadIdx.x] = src[threadIdx.x];
    }
    __syncthreads();

    float2 bv[M2];
#pragma unroll
    for (int i = 0; i < M2; ++i) bv[i] = bstage[t2 * M2 + i];

    float2 acc[NACC];
#pragma unroll
    for (int i = 0; i < NACC; ++i) acc[i] = make_float2(0.f, 0.f);

    const float2* __restrict__ arow =
        reinterpret_cast<const float2*>(fs + (long)b * TOTAL_IN + 64 * L1 * L1 + t1 * M1 * 2);

    sfor<M1>([&](auto I1) {
        constexpr int im1 = decltype(I1)::value;
        const float2 av = arow[im1];  // warp-uniform broadcast LDG
        sfor<M2>([&](auto I2) {
            constexpr int im2 = decltype(I2)::value;
            constexpr int m = (im1 - L1) + (im2 - L2);
            if constexpr (m >= -LHI && m <= LHI) {
                const float pr = av.x * bv[im2].x - av.y * bv[im2].y;
                const float pi = av.x * bv[im2].y + av.y * bv[im2].x;
                sfor<NL>([&](auto J) {
                    constexpr int l = LLO + decltype(J)::value;
                    if constexpr (m >= -l && m <= l) {
                        constexpr float c =
                            (float)cg_coef(L1, im1 - L1, L2, im2 - L2, l, m);
                        if constexpr (c != 0.0f) {
                            constexpr int ao = (l * l - LLO * LLO) + (m + l);
                            acc[ao].x += c * pr;  // FFMA-imm
                            acc[ao].y += c * pi;
                        }
                    }
                });
            }
        });
    });

    const long obatch = (long)b * OUT_POS;

    // ---- phase 1: direct writeback for tuple (l, L1, L2) — per-warp smem transpose ----
    {
        float2* __restrict__ ws = sm + w * 352;
        sfor<NL>([&](auto J) {
            constexpr int l = LLO + decltype(J)::value;
            constexpr int NM = 2 * l + 1;
            constexpr long pbase = outbase(l) + (long)pair_rank(l, L1, L2) * 1024 * NM;

            __syncwarp();
#pragma unroll
            for (int mm = 0; mm < NM; ++mm)
                ws[t2 * NM + mm] = acc[(l * l - LLO * LLO) + mm];
            __syncwarp();

            const float4* __restrict__ s4 = reinterpret_cast<const float4*>(ws);
            float4* __restrict__ o4 = reinterpret_cast<float4*>(
                out + obatch + pbase + (long)(t & ~31) * NM);
            constexpr int CNT4 = 16 * NM;
#pragma unroll
            for (int i = 0; i < (CNT4 + 31) / 32; ++i) {
                const int idx = i * 32 + t2;
                if (CNT4 % 32 == 0 || idx < CNT4) o4[idx] = s4[idx];
            }
        });
    }

    // ---- phase 2: mirror writeback for tuple (l, L2, L1) at t' = t2*32 + t1 ----
    // mirror_acc = (-1)^(L1+L2-l) * acc   (CG symmetry; complex product commutes)
    if constexpr (L1 != L2) {
        sfor<NL>([&](auto J) {
            constexpr int l = LLO + decltype(J)::value;
            constexpr int NM = 2 * l + 1;
            constexpr int SEG = 8 * NM;       // contiguous float2 per t2-segment
            constexpr int SSTR = SEG + 1;     // smem stride (pad kills conflicts)
            constexpr float sgn = ((L1 + L2 - l) & 1) ? -1.f : 1.f;
            constexpr long pbm = outbase(l) + (long)pair_rank(l, L2, L1) * 1024 * NM;

            __syncthreads();
#pragma unroll
            for (int mm = 0; mm < NM; ++mm) {
                const float2 v = acc[(l * l - LLO * LLO) + mm];
                sm[t2 * SSTR + w * NM + mm] = make_float2(sgn * v.x, sgn * v.y);
            }
            __syncthreads();

            // block-wide store: 32 segments of SEG contiguous float2,
            // segment s lands at t' base (s*32 + t1lo) * NM
            float2* __restrict__ mb = out + obatch + pbm + (long)t1lo * NM;
#pragma unroll
            for (int i = 0; i < NM; ++i) {
                const int idx = i * 256 + threadIdx.x;  // < 256*NM = 32*SEG
                const int seg = idx / SEG;
                const int off = idx - seg * SEG;
                mb[(long)seg * (32 * NM) + off] = sm[seg * SSTR + off];
            }
        });
    }
}

// ---------------- kernel: NJOBS jobs x 32 batches x 4 t-tiles, 256 thr/blk ----------------

__global__ void __launch_bounds__(256, 3)
cg_kernel(const float* __restrict__ fs, float2* __restrict__ out) {
    __shared__ float2 bstage[32 * 11];
    __shared__ float2 sm[UNION_F2];

    const int bid = blockIdx.x;
    const int jid = bid >> 7;          // jobs ordered heavy-first
    const int r = bid & 127;
    const int b = r >> 2;
    const int t = ((r & 3) << 8) + threadIdx.x;

    sfor<NJOBS>([&](auto J) {
        constexpr int jj = decltype(J)::value;
        if (jid == jj)
            do_job<JOBS.l1[jj], JOBS.l2[jj], JOBS.llo[jj], JOBS.lhi[jj]>(
                fs, out, sm, bstage, b, t);
    });
}

extern "C" void kernel_launch(void* const* d_in, const int* in_sizes, int n_in,
                              void* d_out, int out_size) {
    const float* fs = (const float*)d_in[0];
    float2* out = (float2*)d_out;
    cg_kernel<<<NJOBS * 128, 256>>>(fs, out);
}